// round 17
// baseline (speedup 1.0000x reference)
#include <cuda_runtime.h>
#include <cuda_fp16.h>
#include <mma.h>

using namespace nvcuda;

#define BATCH 4
#define SEQ   4096
#define DIM   512
#define NTOK  (BATCH*SEQ)

// ---------------- scratch (__device__ globals; no allocations anywhere) ----------------
__device__ __half g_xhi[NTOK*DIM];
__device__ __half g_xlo[NTOK*DIM];
__device__ __half g_wvhi[DIM*DIM];      // Wv hi (lo not needed: V is 1-term)
__device__ __half g_wvlo[DIM*DIM];
__device__ __half g_mhi[DIM*DIM];       // M = Wq @ Wk^T, fp32-accurate, split
__device__ __half g_mlo[DIM*DIM];
__device__ __half g_yhi[NTOK*DIM];      // Y = x @ M
__device__ __half g_ylo[NTOK*DIM];
__device__ __half g_vhi[NTOK*DIM];
__device__ float  g_c1[DIM];            // Wq @ bk
__device__ float  g_c2[DIM];            // Wk @ bq
__device__ float  g_gamma;              // bq . bk
__device__ float  g_alpha[NTOK];        // x @ c1
__device__ float  g_beta[NTOK];         // x @ c2
__device__ float  g_scores[(size_t)BATCH*SEQ*SEQ];
__device__ __half g_p[(size_t)BATCH*SEQ*SEQ];

// ---------------- cp.async helpers ----------------
__device__ __forceinline__ void cp16(void* dst, const void* src) {
    unsigned sa = (unsigned)__cvta_generic_to_shared(dst);
    asm volatile("cp.async.cg.shared.global [%0], [%1], 16;\n" :: "r"(sa), "l"(src));
}
__device__ __forceinline__ void cp_commit() {
    asm volatile("cp.async.commit_group;\n" ::: "memory");
}
__device__ __forceinline__ void cp_wait0() {
    asm volatile("cp.async.wait_group 0;\n" ::: "memory");
}

// ---------------- fp32 -> fp16 hi/lo split ----------------
// which: 0 -> x, 1 -> Wv
__global__ __launch_bounds__(256) void split_kernel(const float* __restrict__ src,
                                                    int which, int n2) {
    int i = blockIdx.x * 256 + threadIdx.x;
    if (i >= n2) return;
    __half *hi, *lo;
    if (which == 0) { hi = g_xhi;  lo = g_xlo;  }
    else            { hi = g_wvhi; lo = g_wvlo; }
    float2 v = reinterpret_cast<const float2*>(src)[i];
    __half h0 = __float2half(v.x);
    __half h1 = __float2half(v.y);
    float l0 = v.x - __half2float(h0);
    float l1 = v.y - __half2float(h1);
    reinterpret_cast<__half2*>(hi)[i] = __halves2half2(h0, h1);
    reinterpret_cast<__half2*>(lo)[i] =
        __halves2half2(__float2half(l0), __float2half(l1));
}

// ---------------- M = Wq @ Wk^T (fp32 accurate, tiny: 512x512x512) ----------------
__global__ __launch_bounds__(256) void m_kernel(const float* __restrict__ Wq,
                                                const float* __restrict__ Wk) {
    __shared__ float As[16][17], Bs[16][17];
    const int tx = threadIdx.x, ty = threadIdx.y;
    const int a = blockIdx.y*16 + ty;
    const int b = blockIdx.x*16 + tx;
    float acc = 0.0f;
    for (int d0 = 0; d0 < DIM; d0 += 16) {
        As[ty][tx] = Wq[(size_t)a*DIM + d0 + tx];
        Bs[ty][tx] = Wk[(size_t)(blockIdx.x*16 + ty)*DIM + d0 + tx];
        __syncthreads();
        #pragma unroll
        for (int dd = 0; dd < 16; dd++) acc += As[ty][dd] * Bs[tx][dd];
        __syncthreads();
    }
    __half h = __float2half(acc);
    g_mhi[(size_t)a*DIM + b] = h;
    g_mlo[(size_t)a*DIM + b] = __float2half(acc - __half2float(h));
}

// ---------------- bias-correction vectors: c1 = Wq@bk, c2 = Wk@bq, gamma = bq.bk ----
__global__ __launch_bounds__(256) void cvec_kernel(const float* __restrict__ Wq,
                                                   const float* __restrict__ Wk,
                                                   const float* __restrict__ bq,
                                                   const float* __restrict__ bk) {
    int k = blockIdx.x*256 + threadIdx.x;
    if (k < DIM) {
        float s1 = 0.0f, s2 = 0.0f;
        for (int d = 0; d < DIM; d++) {
            s1 += Wq[(size_t)k*DIM + d] * bk[d];
            s2 += Wk[(size_t)k*DIM + d] * bq[d];
        }
        g_c1[k] = s1; g_c2[k] = s2;
    }
    if (blockIdx.x == 0 && threadIdx.x == 0) {
        float g = 0.0f;
        for (int d = 0; d < DIM; d++) g += bq[d]*bk[d];
        g_gamma = g;
    }
}

// ---------------- alpha[i] = x_i.c1, beta[i] = x_i.c2 ----------------
__global__ __launch_bounds__(128) void ab_kernel(const float* __restrict__ x) {
    const int row = blockIdx.x, t = threadIdx.x;
    const float* xr = x + (size_t)row*DIM;
    float s1 = 0.0f, s2 = 0.0f;
    for (int k = t; k < DIM; k += 128) {
        float xv = xr[k];
        s1 += xv * g_c1[k];
        s2 += xv * g_c2[k];
    }
    #pragma unroll
    for (int o = 16; o > 0; o >>= 1) {
        s1 += __shfl_xor_sync(0xffffffffu, s1, o);
        s2 += __shfl_xor_sync(0xffffffffu, s2, o);
    }
    __shared__ float r1[4], r2[4];
    if ((t & 31) == 0) { r1[t>>5] = s1; r2[t>>5] = s2; }
    __syncthreads();
    if (t == 0) {
        g_alpha[row] = r1[0]+r1[1]+r1[2]+r1[3];
        g_beta[row]  = r2[0]+r2[1]+r2[2]+r2[3];
    }
}

// =====================================================================================
// GEMM 1: z==0: Y = x @ M (3-term, hi/lo out). z==1: V = x_h @ Wv_h + bv (1-term, hi out)
// 128x128 blocks, cp.async double buffer.
// =====================================================================================
__global__ __launch_bounds__(256) void yv_kernel(const float* __restrict__ bv) {
    __shared__ __half Ah[2][128*24], Al[2][128*24];
    __shared__ __half Bh[2][16*136], Bl[2][16*136];

    const int z  = blockIdx.z;
    const int n0 = blockIdx.x * 128;
    const int i0 = blockIdx.y * 128;
    const int t  = threadIdx.x;
    const int wid = t >> 5, lane = t & 31;
    const int wm = wid >> 1, wn = wid & 1;           // 4x2 warp grid, warp tile 32x64

    const __half* __restrict__ Agh = g_xhi;
    const __half* __restrict__ Agl = g_xlo;
    const __half* __restrict__ Bgh = (z==0) ? g_mhi : g_wvhi;
    const __half* __restrict__ Bgl = g_mlo;          // only used when z==0
    const bool full3 = (z == 0);

    wmma::fragment<wmma::accumulator,16,16,16,float> acc[2][4];
    #pragma unroll
    for (int mi=0; mi<2; mi++)
        #pragma unroll
        for (int ni=0; ni<4; ni++)
            wmma::fill_fragment(acc[mi][ni], 0.0f);

    const int arow = t >> 1, aseg = t & 1;           // A: 128 rows x 2 chunks of 8
    const int brow = t >> 4, bseg = t & 15;          // B: 16 rows x 16 chunks

    auto load_stage = [&](int kt, int s) {
        int k0 = kt * 16;
        cp16(&Ah[s][arow*24 + aseg*8], Agh + (size_t)(i0+arow)*DIM + k0 + aseg*8);
        cp16(&Bh[s][brow*136 + bseg*8], Bgh + (size_t)(k0+brow)*DIM + n0 + bseg*8);
        if (full3) {
            cp16(&Al[s][arow*24 + aseg*8], Agl + (size_t)(i0+arow)*DIM + k0 + aseg*8);
            cp16(&Bl[s][brow*136 + bseg*8], Bgl + (size_t)(k0+brow)*DIM + n0 + bseg*8);
        }
        cp_commit();
    };

    const int KSTEPS = DIM/16;
    load_stage(0, 0);
    for (int kt = 0; kt < KSTEPS; kt++) {
        cp_wait0();
        __syncthreads();
        const int cur = kt & 1;
        if (kt+1 < KSTEPS) load_stage(kt+1, cur^1);

        wmma::fragment<wmma::matrix_a,16,16,16,__half,wmma::row_major> fah[2], fal[2];
        wmma::fragment<wmma::matrix_b,16,16,16,__half,wmma::row_major> fbh[4], fbl[4];
        #pragma unroll
        for (int mi=0; mi<2; mi++) {
            wmma::load_matrix_sync(fah[mi], &Ah[cur][(wm*32+mi*16)*24], 24);
            if (full3)
                wmma::load_matrix_sync(fal[mi], &Al[cur][(wm*32+mi*16)*24], 24);
        }
        #pragma unroll
        for (int ni=0; ni<4; ni++) {
            wmma::load_matrix_sync(fbh[ni], &Bh[cur][wn*64+ni*16], 136);
            if (full3)
                wmma::load_matrix_sync(fbl[ni], &Bl[cur][wn*64+ni*16], 136);
        }
        #pragma unroll
        for (int mi=0; mi<2; mi++)
            #pragma unroll
            for (int ni=0; ni<4; ni++) {
                wmma::mma_sync(acc[mi][ni], fah[mi], fbh[ni], acc[mi][ni]);
                if (full3) {
                    wmma::mma_sync(acc[mi][ni], fah[mi], fbl[ni], acc[mi][ni]);
                    wmma::mma_sync(acc[mi][ni], fal[mi], fbh[ni], acc[mi][ni]);
                }
            }
    }

    // epilogue: stage each 16x16 fragment (reusing Ah smem)
    __syncthreads();
    float* buf = reinterpret_cast<float*>(&Ah[0][0]) + wid * (16*20);
    #pragma unroll
    for (int mi=0; mi<2; mi++)
        #pragma unroll
        for (int ni=0; ni<4; ni++) {
            wmma::store_matrix_sync(buf, acc[mi][ni], 20, wmma::mem_row_major);
            __syncwarp();
            int gi = i0 + wm*32 + mi*16;
            int gn = n0 + wn*64 + ni*16;
            for (int e = lane; e < 256; e += 32) {
                int r = e >> 4, c = e & 15;
                size_t off = (size_t)(gi + r)*DIM + gn + c;
                if (z == 0) {
                    float v = buf[r*20 + c];
                    __half h = __float2half(v);
                    g_yhi[off] = h;
                    g_ylo[off] = __float2half(v - __half2float(h));
                } else {
                    float v = buf[r*20 + c] + bv[gn + c];
                    g_vhi[off] = __float2half(v);
                }
            }
            __syncwarp();
        }
}

// =====================================================================================
// GEMM 2: raw_scores = Y @ x^T * 0.5 (NT). 128x128 blocks, cp.async, fp32 out. 3-term.
// =====================================================================================
__global__ __launch_bounds__(256) void scores_kernel() {
    __shared__ __half Ah[2][128*24], Al[2][128*24];
    __shared__ __half Bh[2][128*24], Bl[2][128*24];

    const int b  = blockIdx.z;
    const int j0 = blockIdx.x * 128;
    const int i0 = blockIdx.y * 128;
    const int t  = threadIdx.x;
    const int wid = t >> 5;
    const int wm = wid >> 1, wn = wid & 1;

    const __half* __restrict__ Agh = g_yhi + (size_t)b*SEQ*DIM;
    const __half* __restrict__ Agl = g_ylo + (size_t)b*SEQ*DIM;
    const __half* __restrict__ Bgh = g_xhi + (size_t)b*SEQ*DIM;
    const __half* __restrict__ Bgl = g_xlo + (size_t)b*SEQ*DIM;

    wmma::fragment<wmma::accumulator,16,16,16,float> acc[2][4];
    #pragma unroll
    for (int mi=0; mi<2; mi++)
        #pragma unroll
        for (int ni=0; ni<4; ni++)
            wmma::fill_fragment(acc[mi][ni], 0.0f);

    const int arow = t >> 1, aseg = t & 1;   // both tiles: 128 rows x 2 chunks

    auto load_stage = [&](int kt, int s) {
        int k0 = kt * 16;
        cp16(&Ah[s][arow*24 + aseg*8], Agh + (size_t)(i0+arow)*DIM + k0 + aseg*8);
        cp16(&Al[s][arow*24 + aseg*8], Agl + (size_t)(i0+arow)*DIM + k0 + aseg*8);
        cp16(&Bh[s][arow*24 + aseg*8], Bgh + (size_t)(j0+arow)*DIM + k0 + aseg*8);
        cp16(&Bl[s][arow*24 + aseg*8], Bgl + (size_t)(j0+arow)*DIM + k0 + aseg*8);
        cp_commit();
    };

    const int KSTEPS = DIM/16;
    load_stage(0, 0);
    for (int kt = 0; kt < KSTEPS; kt++) {
        cp_wait0();
        __syncthreads();
        const int cur = kt & 1;
        if (kt+1 < KSTEPS) load_stage(kt+1, cur^1);

        wmma::fragment<wmma::matrix_a,16,16,16,__half,wmma::row_major> fah[2], fal[2];
        wmma::fragment<wmma::matrix_b,16,16,16,__half,wmma::col_major> fbh[4], fbl[4];
        #pragma unroll
        for (int mi=0; mi<2; mi++) {
            wmma::load_matrix_sync(fah[mi], &Ah[cur][(wm*32+mi*16)*24], 24);
            wmma::load_matrix_sync(fal[mi], &Al[cur][(wm*32+mi*16)*24], 24);
        }
        #pragma unroll
        for (int ni=0; ni<4; ni++) {
            wmma::load_matrix_sync(fbh[ni], &Bh[cur][(wn*64+ni*16)*24], 24);
            wmma::load_matrix_sync(fbl[ni], &Bl[cur][(wn*64+ni*16)*24], 24);
        }
        #pragma unroll
        for (int mi=0; mi<2; mi++)
            #pragma unroll
            for (int ni=0; ni<4; ni++) {
                wmma::mma_sync(acc[mi][ni], fah[mi], fbh[ni], acc[mi][ni]);
                wmma::mma_sync(acc[mi][ni], fah[mi], fbl[ni], acc[mi][ni]);
                wmma::mma_sync(acc[mi][ni], fal[mi], fbh[ni], acc[mi][ni]);
            }
    }

    #pragma unroll
    for (int mi=0; mi<2; mi++)
        #pragma unroll
        for (int ni=0; ni<4; ni++) {
            #pragma unroll
            for (int e = 0; e < acc[mi][ni].num_elements; e++)
                acc[mi][ni].x[e] *= 0.5f;    // scale = batch/2 = 2 -> divide by 2
            float* Cp = g_scores + (size_t)b*SEQ*SEQ
                        + (size_t)(i0 + wm*32 + mi*16)*SEQ + (j0 + wn*64 + ni*16);
            wmma::store_matrix_sync(Cp, acc[mi][ni], SEQ, wmma::mem_row_major);
        }
}

// ---------------- softmax over rows of 4096 (+ bias corrections), writes P fp16 -------
__global__ __launch_bounds__(256) void softmax_kernel() {
    __shared__ float red[40];
    const int t = threadIdx.x;
    const int lane = t & 31, warp = t >> 5;
    size_t base = (size_t)blockIdx.x * SEQ;
    const float4* src4 = reinterpret_cast<const float4*>(g_scores + base);
    const float4* b4 = reinterpret_cast<const float4*>(g_beta + (blockIdx.x / SEQ) * SEQ);
    const float rcorr = 0.5f * (g_alpha[blockIdx.x] + g_gamma);

    float4 v[4];
    float mx = -3.0e38f;
    #pragma unroll
    for (int q = 0; q < 4; q++) {
        v[q] = src4[t + 256*q];
        float4 bb = b4[t + 256*q];
        v[q].x += rcorr + 0.5f*bb.x;
        v[q].y += rcorr + 0.5f*bb.y;
        v[q].z += rcorr + 0.5f*bb.z;
        v[q].w += rcorr + 0.5f*bb.w;
        mx = fmaxf(mx, fmaxf(fmaxf(v[q].x, v[q].y), fmaxf(v[q].z, v[q].w)));
    }
    #pragma unroll
    for (int o = 16; o > 0; o >>= 1) mx = fmaxf(mx, __shfl_xor_sync(0xffffffffu, mx, o));
    if (lane == 0) red[warp] = mx;
    __syncthreads();
    if (t == 0) {
        float m = red[0];
        #pragma unroll
        for (int w = 1; w < 8; w++) m = fmaxf(m, red[w]);
        red[32] = m;
    }
    __syncthreads();
    mx = red[32];

    float sum = 0.0f;
    #pragma unroll
    for (int q = 0; q < 4; q++) {
        v[q].x = expf(v[q].x - mx);
        v[q].y = expf(v[q].y - mx);
        v[q].z = expf(v[q].z - mx);
        v[q].w = expf(v[q].w - mx);
        sum += (v[q].x + v[q].y) + (v[q].z + v[q].w);
    }
    #pragma unroll
    for (int o = 16; o > 0; o >>= 1) sum += __shfl_xor_sync(0xffffffffu, sum, o);
    if (lane == 0) red[8 + warp] = sum;
    __syncthreads();
    if (t == 0) {
        float s = 0.0f;
        #pragma unroll
        for (int w = 0; w < 8; w++) s += red[8 + w];
        red[33] = 1.0f / s;
    }
    __syncthreads();
    float inv = red[33];

    __half2* ph = reinterpret_cast<__half2*>(g_p + base);
    #pragma unroll
    for (int q = 0; q < 4; q++) {
        float p0 = v[q].x * inv, p1 = v[q].y * inv, p2 = v[q].z * inv, p3 = v[q].w * inv;
        int pi = 2*(t + 256*q);
        ph[pi]   = __floats2half2_rn(p0, p1);
        ph[pi+1] = __floats2half2_rn(p2, p3);
    }
}

// =====================================================================================
// GEMM 3: Z = P @ V (NN), K = 4096. 1-term: P_h * V_h.
// =====================================================================================
__global__ __launch_bounds__(256) void z_kernel(float* __restrict__ out) {
    __shared__ __half As[2][128*24];
    __shared__ __half Bs[2][16*136];

    const int b  = blockIdx.z;
    const int n0 = blockIdx.x * 128;
    const int i0 = blockIdx.y * 128;
    const int t  = threadIdx.x;
    const int wid = t >> 5;
    const int wm = wid >> 1, wn = wid & 1;

    const __half* __restrict__ Ag = g_p   + (size_t)b*SEQ*SEQ;
    const __half* __restrict__ Bg = g_vhi + (size_t)b*SEQ*DIM;

    wmma::fragment<wmma::accumulator,16,16,16,float> acc[2][4];
    #pragma unroll
    for (int mi=0; mi<2; mi++)
        #pragma unroll
        for (int ni=0; ni<4; ni++)
            wmma::fill_fragment(acc[mi][ni], 0.0f);

    const int arow = t >> 1, aseg = t & 1;   // A: 128 rows x 2 chunks
    const int brow = t >> 4, bseg = t & 15;  // B: 16 rows x 16 chunks

    auto load_stage = [&](int kt, int s) {
        int k0 = kt * 16;
        cp16(&As[s][arow*24 + aseg*8], Ag + (size_t)(i0+arow)*SEQ + k0 + aseg*8);
        cp16(&Bs[s][brow*136 + bseg*8], Bg + (size_t)(k0+brow)*DIM + n0 + bseg*8);
        cp_commit();
    };

    const int KSTEPS = SEQ/16;
    load_stage(0, 0);
    for (int kt = 0; kt < KSTEPS; kt++) {
        cp_wait0();
        __syncthreads();
        const int cur = kt & 1;
        if (kt+1 < KSTEPS) load_stage(kt+1, cur^1);

        wmma::fragment<wmma::matrix_a,16,16,16,__half,wmma::row_major> fa[2];
        wmma::fragment<wmma::matrix_b,16,16,16,__half,wmma::row_major> fb[4];
        #pragma unroll
        for (int mi=0; mi<2; mi++)
            wmma::load_matrix_sync(fa[mi], &As[cur][(wm*32+mi*16)*24], 24);
        #pragma unroll
        for (int ni=0; ni<4; ni++)
            wmma::load_matrix_sync(fb[ni], &Bs[cur][wn*64+ni*16], 136);
        #pragma unroll
        for (int mi=0; mi<2; mi++)
            #pragma unroll
            for (int ni=0; ni<4; ni++)
                wmma::mma_sync(acc[mi][ni], fa[mi], fb[ni], acc[mi][ni]);
    }

    #pragma unroll
    for (int mi=0; mi<2; mi++)
        #pragma unroll
        for (int ni=0; ni<4; ni++) {
            float* Cp = out + (size_t)b*SEQ*DIM
                        + (size_t)(i0 + wm*32 + mi*16)*DIM + (n0 + wn*64 + ni*16);
            wmma::store_matrix_sync(Cp, acc[mi][ni], DIM, wmma::mem_row_major);
        }
}

// ---------------- launch ----------------
extern "C" void kernel_launch(void* const* d_in, const int* in_sizes, int n_in,
                              void* d_out, int out_size) {
    (void)in_sizes; (void)n_in; (void)out_size;
    const float* x  = (const float*)d_in[0];
    const float* Wq = (const float*)d_in[1];
    const float* bq = (const float*)d_in[2];
    const float* Wk = (const float*)d_in[3];
    const float* bk = (const float*)d_in[4];
    const float* Wv = (const float*)d_in[5];
    const float* bv = (const float*)d_in[6];
    float* out = (float*)d_out;

    const int nx2 = NTOK*DIM/2;
    const int nw2 = DIM*DIM/2;
    split_kernel<<<(nx2 + 255)/256, 256>>>(x,  0, nx2);
    split_kernel<<<(nw2 + 255)/256, 256>>>(Wv, 1, nw2);

    m_kernel<<<dim3(DIM/16, DIM/16), dim3(16,16)>>>(Wq, Wk);
    cvec_kernel<<<2, 256>>>(Wq, Wk, bq, bk);
    ab_kernel<<<NTOK, 128>>>(x);

    yv_kernel<<<dim3(DIM/128, NTOK/128, 2), 256>>>(bv);
    scores_kernel<<<dim3(SEQ/128, SEQ/128, BATCH), 256>>>();
    softmax_kernel<<<NTOK, 256>>>();
    z_kernel<<<dim3(DIM/128, SEQ/128, BATCH), 256>>>(out);
}